// round 8
// baseline (speedup 1.0000x reference)
#include <cuda_runtime.h>
#include <cuda_fp16.h>
#include <math.h>
#include <stdint.h>

#define B_  8
#define S_  1024
#define H_  1024
#define NH_ 16
#define HD_ 64
#define BH_ (B_*NH_)   // 128

// fp16 hi/lo split scratch (all row-major halfs)
__device__ __half g_xh[(size_t)8192*1024];
__device__ __half g_xl[(size_t)8192*1024];
__device__ __half g_wh[(size_t)1024*3072];
__device__ __half g_wl[(size_t)1024*3072];
__device__ __half g_qh[(size_t)BH_*S_*HD_];   // pre-scaled x8
__device__ __half g_ql[(size_t)BH_*S_*HD_];
__device__ __half g_kh[(size_t)BH_*S_*HD_];
__device__ __half g_kl[(size_t)BH_*S_*HD_];
__device__ __half g_vh[(size_t)BH_*S_*HD_];
__device__ __half g_vl[(size_t)BH_*S_*HD_];

// ---------------------------------------------------------------------------
// helpers
// ---------------------------------------------------------------------------
__device__ __forceinline__ unsigned smem_u32(const void* p) {
    return (unsigned)__cvta_generic_to_shared(p);
}
__device__ __forceinline__ void ldm_x4(unsigned* r, unsigned addr) {
    asm volatile("ldmatrix.sync.aligned.m8n8.x4.shared.b16 {%0,%1,%2,%3}, [%4];"
        : "=r"(r[0]), "=r"(r[1]), "=r"(r[2]), "=r"(r[3]) : "r"(addr));
}
__device__ __forceinline__ void ldm_x4t(unsigned* r, unsigned addr) {
    asm volatile("ldmatrix.sync.aligned.m8n8.x4.trans.shared.b16 {%0,%1,%2,%3}, [%4];"
        : "=r"(r[0]), "=r"(r[1]), "=r"(r[2]), "=r"(r[3]) : "r"(addr));
}
// f32-accumulate mma (half rate, for dominant hh terms)
__device__ __forceinline__ void mma16(float* d, const unsigned* a, const unsigned* b) {
    asm volatile(
        "mma.sync.aligned.m16n8k16.row.col.f32.f16.f16.f32 "
        "{%0,%1,%2,%3}, {%4,%5,%6,%7}, {%8,%9}, {%0,%1,%2,%3};\n"
        : "+f"(d[0]), "+f"(d[1]), "+f"(d[2]), "+f"(d[3])
        : "r"(a[0]), "r"(a[1]), "r"(a[2]), "r"(a[3]), "r"(b[0]), "r"(b[1]));
}
// f16-accumulate mma (full rate, for tiny correction terms)
__device__ __forceinline__ void mma16h(unsigned* d, const unsigned* a, const unsigned* b) {
    asm volatile(
        "mma.sync.aligned.m16n8k16.row.col.f16.f16.f16.f16 "
        "{%0,%1}, {%2,%3,%4,%5}, {%6,%7}, {%0,%1};\n"
        : "+r"(d[0]), "+r"(d[1])
        : "r"(a[0]), "r"(a[1]), "r"(a[2]), "r"(a[3]), "r"(b[0]), "r"(b[1]));
}
// fold packed-half correction into f32 accumulator quad
__device__ __forceinline__ void fold_cor(float* d, const unsigned* c) {
    float2 f0 = __half22float2(*(const __half2*)&c[0]);
    float2 f1 = __half22float2(*(const __half2*)&c[1]);
    d[0] += f0.x; d[1] += f0.y; d[2] += f1.x; d[3] += f1.y;
}
#define CP16(dst, src) \
    asm volatile("cp.async.cg.shared.global [%0], [%1], 16;" \
                 :: "r"((uint32_t)(dst)), "l"(src) : "memory")
#define CP_COMMIT() asm volatile("cp.async.commit_group;" ::: "memory")
#define CP_WAIT(n)  asm volatile("cp.async.wait_group %0;" :: "n"(n) : "memory")

__device__ __forceinline__ void split_h2(float x, float y, __half2& h, __half2& l) {
    h = __float22half2_rn(make_float2(x, y));
    float2 f = __half22float2(h);
    l = __float22half2_rn(make_float2(x - f.x, y - f.y));
}

// ---------------------------------------------------------------------------
// Kernel 0: preconvert X and W to fp16 hi/lo
// ---------------------------------------------------------------------------
#define NX4 2097152   // 8M floats / 4
#define NW4 786432    // 3M floats / 4
__global__ __launch_bounds__(256)
void preconv_kernel(const float* __restrict__ X, const float* __restrict__ W) {
    int idx = blockIdx.x * 256 + threadIdx.x;
    if (idx < NX4) {
        float4 v = ((const float4*)X)[idx];
        __half2 h0, l0, h1, l1;
        split_h2(v.x, v.y, h0, l0);
        split_h2(v.z, v.w, h1, l1);
        *(__half2*)(g_xh + idx * 4)     = h0;
        *(__half2*)(g_xh + idx * 4 + 2) = h1;
        *(__half2*)(g_xl + idx * 4)     = l0;
        *(__half2*)(g_xl + idx * 4 + 2) = l1;
    } else if (idx < NX4 + NW4) {
        int j = idx - NX4;
        float4 v = ((const float4*)W)[j];
        __half2 h0, l0, h1, l1;
        split_h2(v.x, v.y, h0, l0);
        split_h2(v.z, v.w, h1, l1);
        *(__half2*)(g_wh + j * 4)     = h0;
        *(__half2*)(g_wh + j * 4 + 2) = h1;
        *(__half2*)(g_wl + j * 4)     = l0;
        *(__half2*)(g_wl + j * 4 + 2) = l1;
    }
}

// ---------------------------------------------------------------------------
// Kernel 1: QKV GEMM. hh pass -> f32 acc; hl+lh passes -> f16 acc.
// 128x128x32 tile, 256 threads (8 warps, 32x64 warp tile), cp.async 2-stage.
// ---------------------------------------------------------------------------
#define ASTRH 40
#define BSTRH 136
#define A_BYTES (128 * ASTRH * 2)   // 10240
#define B_BYTES (32 * BSTRH * 2)    // 8704
#define BUFB (2 * A_BYTES + 2 * B_BYTES)   // 37888

__global__ __launch_bounds__(256)
void qkv_gemm_kernel(const float* __restrict__ bias) {
    extern __shared__ __align__(16) char smem[];

    const int tid = threadIdx.x;
    const int warp = tid >> 5, lane = tid & 31;
    const int g = lane >> 2, tg = lane & 3;
    const int lr = lane & 15;
    const int lc = (lane & 16) >> 1;
    const int wm = (warp & 3) * 32, wn = (warp >> 2) * 64;
    const int bm = blockIdx.y * 128, bn = blockIdx.x * 128;

    float    acc[2][8][4];   // hh (f32 acc)
    unsigned cor[2][8][2];   // hl+lh corrections (f16 acc, packed)
#pragma unroll
    for (int mt = 0; mt < 2; mt++)
#pragma unroll
        for (int nt = 0; nt < 8; nt++) {
#pragma unroll
            for (int i = 0; i < 4; i++) acc[mt][nt][i] = 0.f;
            cor[mt][nt][0] = 0u; cor[mt][nt][1] = 0u;
        }

    auto stage = [&](int c, int buf) {
        const int k0 = c * 32;
        uint32_t base = smem_u32(smem) + buf * BUFB;
        uint32_t ah = base, al = base + A_BYTES;
        uint32_t bh = base + 2 * A_BYTES, bl = bh + B_BYTES;
#pragma unroll
        for (int r = 0; r < 2; r++) {
            int l = tid + 256 * r;          // 0..511
            int row = l >> 2, c4 = l & 3;   // A: 128 rows x 4 chunks of 8 halfs
            size_t src = (size_t)(bm + row) * 1024 + k0 + c4 * 8;
            uint32_t d = (uint32_t)(row * ASTRH + c4 * 8) * 2;
            CP16(ah + d, g_xh + src);
            CP16(al + d, g_xl + src);
        }
#pragma unroll
        for (int r = 0; r < 2; r++) {
            int l = tid + 256 * r;
            int row = l >> 4, c16 = l & 15; // B: 32 rows x 16 chunks
            size_t src = (size_t)(k0 + row) * 3072 + bn + c16 * 8;
            uint32_t d = (uint32_t)(row * BSTRH + c16 * 8) * 2;
            CP16(bh + d, g_wh + src);
            CP16(bl + d, g_wl + src);
        }
    };

    stage(0, 0);
    CP_COMMIT();

    for (int c = 0; c < 32; c++) {
        const int buf = c & 1;
        if (c + 1 < 32) {
            stage(c + 1, buf ^ 1);
            CP_COMMIT();
            CP_WAIT(1);
        } else {
            CP_WAIT(0);
        }
        __syncthreads();

        uint32_t base = smem_u32(smem) + buf * BUFB;
        uint32_t ah = base, al = base + A_BYTES;
        uint32_t bh = base + 2 * A_BYTES, bl = bh + B_BYTES;

#pragma unroll
        for (int ks = 0; ks < 2; ks++) {
            int kb = ks * 16;
            unsigned ahf[2][4], alf[2][4];
#pragma unroll
            for (int mt = 0; mt < 2; mt++) {
                uint32_t off = (uint32_t)((wm + mt * 16 + lr) * ASTRH + kb + lc) * 2;
                ldm_x4(ahf[mt], ah + off);
                ldm_x4(alf[mt], al + off);
            }
#pragma unroll
            for (int nt2 = 0; nt2 < 4; nt2++) {
                uint32_t off = (uint32_t)((kb + lr) * BSTRH + wn + nt2 * 16 + lc) * 2;
                unsigned bhr[4], blr[4];
                ldm_x4t(bhr, bh + off);
                ldm_x4t(blr, bl + off);
#pragma unroll
                for (int p = 0; p < 2; p++) {
                    int nt = nt2 * 2 + p;
                    unsigned bhp[2] = { bhr[2 * p], bhr[2 * p + 1] };
                    unsigned blp[2] = { blr[2 * p], blr[2 * p + 1] };
#pragma unroll
                    for (int mt = 0; mt < 2; mt++) {
                        mma16 (acc[mt][nt], ahf[mt], bhp);   // hi*hi  (f32 acc)
                        mma16h(cor[mt][nt], ahf[mt], blp);   // hi*lo  (f16 acc)
                        mma16h(cor[mt][nt], alf[mt], bhp);   // lo*hi  (f16 acc)
                    }
                }
            }
        }
        __syncthreads();   // all warps done reading before overwrite
    }

    // epilogue: fold corrections, bias, hi/lo split + scatter
#pragma unroll
    for (int nt = 0; nt < 8; nt++) {
        int n0 = bn + wn + nt * 8 + 2 * tg;
        float bia0 = bias[n0], bia1 = bias[n0 + 1];
        int nh  = n0 / 192;
        int rem = n0 - nh * 192;
        int which = rem >> 6;
        int hd = rem & 63;
        __half* ph = (which == 0) ? g_qh : ((which == 1) ? g_kh : g_vh);
        __half* pl = (which == 0) ? g_ql : ((which == 1) ? g_kl : g_vl);
        float sc = (which == 0) ? 8.f : 1.f;
#pragma unroll
        for (int mt = 0; mt < 2; mt++) {
            fold_cor(acc[mt][nt], cor[mt][nt]);
#pragma unroll
            for (int h = 0; h < 2; h++) {
                int m = bm + wm + mt * 16 + g + h * 8;
                int b = m >> 10, s = m & 1023;
                float vx = (acc[mt][nt][h * 2 + 0] + bia0) * sc;
                float vy = (acc[mt][nt][h * 2 + 1] + bia1) * sc;
                __half2 hh, ll;
                split_h2(vx, vy, hh, ll);
                size_t dst = (((size_t)(b * NH_ + nh)) * S_ + s) * HD_ + hd;
                *(__half2*)(ph + dst) = hh;
                *(__half2*)(pl + dst) = ll;
            }
        }
    }
}

// ---------------------------------------------------------------------------
// Kernel 2: fused flash attention. 256 threads (8 warps x 16 queries).
// QK: hh f32-acc + (hl,lh) f16-acc. PV: V_hi f32-acc + V_lo f16-acc.
// ---------------------------------------------------------------------------
#define QSH 72

__global__ __launch_bounds__(256)
void attn_kernel(const int* __restrict__ mask, float* __restrict__ out) {
    extern __shared__ char smc[];
    __half* Qh = (__half*)smc;          // [128][72]
    __half* Ql = Qh + 128 * QSH;
    __half* Kh = Ql + 128 * QSH;        // [64][72]
    __half* Kl = Kh + 64 * QSH;
    __half* Vh = Kl + 64 * QSH;         // [64][72]
    __half* Vl = Vh + 64 * QSH;
    __half* Ps = Vl + 64 * QSH;         // [128][72]
    int*    mk = (int*)(Ps + 128 * QSH);   // [1024]

    const int bh = blockIdx.y, b = bh >> 4, nh = bh & 15;
    const int q0 = blockIdx.x * 128;
    const int tid = threadIdx.x;
    const int warp = tid >> 5, lane = tid & 31;
    const int g = lane >> 2, tg = lane & 3;
    const int lr = lane & 15;
    const int lc = (lane & 16) >> 1;
    const int wq = warp * 16;

    const unsigned qh_b = smem_u32(Qh), ql_b = smem_u32(Ql);
    const unsigned kh_b = smem_u32(Kh), kl_b = smem_u32(Kl);
    const unsigned vh_b = smem_u32(Vh), vl_b = smem_u32(Vl);
    const unsigned ps_b = smem_u32(Ps);

    // stage Q (pre-scaled) via cp.async + mask
    {
        const size_t qbase = ((size_t)bh * S_ + q0) * HD_;
#pragma unroll
        for (int r = 0; r < 4; r++) {
            int l = tid + 256 * r;          // 0..1023
            int row = l >> 3, c8 = l & 7;   // 128 rows x 8 chunks
            size_t src = qbase + row * 64 + c8 * 8;
            uint32_t d = (uint32_t)(row * QSH + c8 * 8) * 2;
            CP16(qh_b + d, g_qh + src);
            CP16(ql_b + d, g_ql + src);
        }
        CP_COMMIT();
        *(int4*)&mk[tid * 4] = *(const int4*)&mask[b * S_ + tid * 4];
    }

    float O[8][4];
    float mrow[2], lrow[2];
    mrow[0] = -INFINITY; mrow[1] = -INFINITY;
    lrow[0] = 0.f;       lrow[1] = 0.f;
#pragma unroll
    for (int nt = 0; nt < 8; nt++)
#pragma unroll
        for (int i = 0; i < 4; i++) O[nt][i] = 0.f;

    for (int kt = 0; kt < 16; kt++) {
        __syncthreads();   // consumers of previous K/V done
        {
            const size_t kbase = ((size_t)bh * S_ + kt * 64) * HD_;
#pragma unroll
            for (int r = 0; r < 2; r++) {
                int l = tid + 256 * r;          // 0..511
                int row = l >> 3, c8 = l & 7;   // 64 rows x 8 chunks
                size_t src = kbase + row * 64 + c8 * 8;
                uint32_t d = (uint32_t)(row * QSH + c8 * 8) * 2;
                CP16(kh_b + d, g_kh + src);
                CP16(kl_b + d, g_kl + src);
                CP16(vh_b + d, g_vh + src);
                CP16(vl_b + d, g_vl + src);
            }
        }
        CP_COMMIT();
        CP_WAIT(0);
        __syncthreads();

        // ---- S = Q @ K^T: hh f32-acc, corrections f16-acc ----
        float    S[8][4];
        unsigned C[8][2];
#pragma unroll
        for (int nt = 0; nt < 8; nt++) {
#pragma unroll
            for (int i = 0; i < 4; i++) S[nt][i] = 0.f;
            C[nt][0] = 0u; C[nt][1] = 0u;
        }

#pragma unroll
        for (int ks = 0; ks < 4; ks++) {
            int kb = ks * 16;
            unsigned qhf[4], qlf[4];
            {
                uint32_t off = (uint32_t)((wq + lr) * QSH + kb + lc) * 2;
                ldm_x4(qhf, qh_b + off);
                ldm_x4(qlf, ql_b + off);
            }
#pragma unroll
            for (int nt2 = 0; nt2 < 4; nt2++) {
                uint32_t off = (uint32_t)((nt2 * 16 + lr) * QSH + kb + lc) * 2;
                unsigned khr[4], klr[4];
                ldm_x4(khr, kh_b + off);
                ldm_x4(klr, kl_b + off);
#pragma unroll
                for (int p = 0; p < 2; p++) {
                    int nt = nt2 * 2 + p;
                    unsigned bhp[2] = { khr[p], khr[p + 2] };
                    unsigned blp[2] = { klr[p], klr[p + 2] };
                    mma16 (S[nt], qhf, bhp);   // hh (f32 acc)
                    mma16h(C[nt], qhf, blp);   // hl (f16 acc)
                    mma16h(C[nt], qlf, bhp);   // lh (f16 acc)
                }
            }
        }
#pragma unroll
        for (int nt = 0; nt < 8; nt++) fold_cor(S[nt], C[nt]);

        // ---- mask ----
#pragma unroll
        for (int nt = 0; nt < 8; nt++) {
            int c = kt * 64 + nt * 8 + 2 * tg;
            if (mk[c])     { S[nt][0] = -10000.f; S[nt][2] = -10000.f; }
            if (mk[c + 1]) { S[nt][1] = -10000.f; S[nt][3] = -10000.f; }
        }

        // ---- online softmax ----
#pragma unroll
        for (int h = 0; h < 2; h++) {
            float rm = -INFINITY;
#pragma unroll
            for (int nt = 0; nt < 8; nt++)
                rm = fmaxf(rm, fmaxf(S[nt][2 * h], S[nt][2 * h + 1]));
            rm = fmaxf(rm, __shfl_xor_sync(0xffffffffu, rm, 1));
            rm = fmaxf(rm, __shfl_xor_sync(0xffffffffu, rm, 2));
            float mn = fmaxf(mrow[h], rm);
            float corr = __expf(mrow[h] - mn);
            mrow[h] = mn;
            float rs = 0.f;
#pragma unroll
            for (int nt = 0; nt < 8; nt++) {
                float e0 = __expf(S[nt][2 * h] - mn);
                float e1 = __expf(S[nt][2 * h + 1] - mn);
                S[nt][2 * h] = e0; S[nt][2 * h + 1] = e1;
                rs += e0 + e1;
            }
            rs += __shfl_xor_sync(0xffffffffu, rs, 1);
            rs += __shfl_xor_sync(0xffffffffu, rs, 2);
            lrow[h] = lrow[h] * corr + rs;
#pragma unroll
            for (int nt = 0; nt < 8; nt++) {
                O[nt][2 * h]     *= corr;
                O[nt][2 * h + 1] *= corr;
            }
        }

        // ---- stash P fp16 (warp-private rows) ----
#pragma unroll
        for (int h = 0; h < 2; h++) {
            int row = wq + g + h * 8;
#pragma unroll
            for (int nt = 0; nt < 8; nt++) {
                __half2 p2 = __float22half2_rn(
                    make_float2(S[nt][2 * h], S[nt][2 * h + 1]));
                *(__half2*)&Ps[row * QSH + nt * 8 + 2 * tg] = p2;
            }
        }
        __syncwarp();

        // ---- O += P @ V: V_hi f32-acc, V_lo f16-acc ----
        unsigned OC[8][2];
#pragma unroll
        for (int nt = 0; nt < 8; nt++) { OC[nt][0] = 0u; OC[nt][1] = 0u; }

#pragma unroll
        for (int ks = 0; ks < 4; ks++) {
            int kb = ks * 16;
            unsigned pf[4];
            {
                uint32_t off = (uint32_t)((wq + lr) * QSH + kb + lc) * 2;
                ldm_x4(pf, ps_b + off);
            }
#pragma unroll
            for (int nt2 = 0; nt2 < 4; nt2++) {
                uint32_t off = (uint32_t)((kb + lr) * QSH + nt2 * 16 + lc) * 2;
                unsigned vhr[4], vlr[4];
                ldm_x4t(vhr, vh_b + off);
                ldm_x4t(vlr, vl_b + off);
#pragma unroll
                for (int p = 0; p < 2; p++) {
                    int nt = nt2 * 2 + p;
                    unsigned bhp[2] = { vhr[2 * p], vhr[2 * p + 1] };
                    unsigned blp[2] = { vlr[2 * p], vlr[2 * p + 1] };
                    mma16 (O[nt],  pf, bhp);   // P*V_hi (f32 acc)
                    mma16h(OC[nt], pf, blp);   // P*V_lo (f16 acc)
                }
            }
        }
#pragma unroll
        for (int nt = 0; nt < 8; nt++) fold_cor(O[nt], OC[nt]);
    }

    // epilogue
#pragma unroll
    for (int h = 0; h < 2; h++) {
        float inv = 1.f / lrow[h];
        int q = q0 + wq + g + h * 8;
        float* op = out + ((size_t)(b * S_ + q)) * H_ + nh * 64;
#pragma unroll
        for (int nt = 0; nt < 8; nt++) {
            float2 v;
            v.x = O[nt][2 * h] * inv;
            v.y = O[nt][2 * h + 1] * inv;
            *(float2*)(op + nt * 8 + 2 * tg) = v;
        }
    }
}

// ---------------------------------------------------------------------------
extern "C" void kernel_launch(void* const* d_in, const int* in_sizes, int n_in,
                              void* d_out, int out_size) {
    const float* hidden = (const float*)d_in[0];   // [8,1024,1024]
    const int*   mask   = (const int*)  d_in[1];   // [8,1,1,1024]
    const float* w_qkv  = (const float*)d_in[2];   // [1024,3072]
    const float* b_qkv  = (const float*)d_in[3];   // [3072]
    float* out = (float*)d_out;

    (void)in_sizes; (void)n_in; (void)out_size;

    // 0: preconvert X, W -> fp16 hi/lo
    int n4 = NX4 + NW4;
    preconv_kernel<<<(n4 + 255) / 256, 256>>>(hidden, w_qkv);

    // 1: QKV GEMM
    size_t smem1 = 2 * (size_t)BUFB;               // 75776
    cudaFuncSetAttribute(qkv_gemm_kernel,
                         cudaFuncAttributeMaxDynamicSharedMemorySize, (int)smem1);
    dim3 g1(3072 / 128, 8192 / 128);               // 24 x 64
    qkv_gemm_kernel<<<g1, 256, smem1>>>(b_qkv);

    // 2: attention
    size_t smem2 = (size_t)(128 * QSH * 3 + 64 * QSH * 4) * sizeof(__half)
                 + 1024 * sizeof(int);             // 96256
    cudaFuncSetAttribute(attn_kernel,
                         cudaFuncAttributeMaxDynamicSharedMemorySize, (int)smem2);
    dim3 g2(S_ / 128, BH_);                         // 8 x 128
    attn_kernel<<<g2, 256, smem2>>>(mask, out);
}

// round 9
// speedup vs baseline: 1.1424x; 1.1424x over previous
#include <cuda_runtime.h>
#include <cuda_fp16.h>
#include <math.h>
#include <stdint.h>

#define B_  8
#define S_  1024
#define H_  1024
#define NH_ 16
#define HD_ 64
#define BH_ (B_*NH_)   // 128

// fp16 hi/lo split scratch (all row-major halfs)
__device__ __half g_xh[(size_t)8192*1024];
__device__ __half g_xl[(size_t)8192*1024];
__device__ __half g_wh[(size_t)1024*3072];
__device__ __half g_wl[(size_t)1024*3072];
__device__ __half g_qh[(size_t)BH_*S_*HD_];   // pre-scaled x8
__device__ __half g_ql[(size_t)BH_*S_*HD_];
__device__ __half g_kh[(size_t)BH_*S_*HD_];
__device__ __half g_kl[(size_t)BH_*S_*HD_];
__device__ __half g_vh[(size_t)BH_*S_*HD_];
__device__ __half g_vl[(size_t)BH_*S_*HD_];

// ---------------------------------------------------------------------------
// helpers
// ---------------------------------------------------------------------------
__device__ __forceinline__ unsigned smem_u32(const void* p) {
    return (unsigned)__cvta_generic_to_shared(p);
}
__device__ __forceinline__ void ldm_x4(unsigned* r, unsigned addr) {
    asm volatile("ldmatrix.sync.aligned.m8n8.x4.shared.b16 {%0,%1,%2,%3}, [%4];"
        : "=r"(r[0]), "=r"(r[1]), "=r"(r[2]), "=r"(r[3]) : "r"(addr));
}
__device__ __forceinline__ void ldm_x4t(unsigned* r, unsigned addr) {
    asm volatile("ldmatrix.sync.aligned.m8n8.x4.trans.shared.b16 {%0,%1,%2,%3}, [%4];"
        : "=r"(r[0]), "=r"(r[1]), "=r"(r[2]), "=r"(r[3]) : "r"(addr));
}
__device__ __forceinline__ void mma16(float* d, const unsigned* a, const unsigned* b) {
    asm volatile(
        "mma.sync.aligned.m16n8k16.row.col.f32.f16.f16.f32 "
        "{%0,%1,%2,%3}, {%4,%5,%6,%7}, {%8,%9}, {%0,%1,%2,%3};\n"
        : "+f"(d[0]), "+f"(d[1]), "+f"(d[2]), "+f"(d[3])
        : "r"(a[0]), "r"(a[1]), "r"(a[2]), "r"(a[3]), "r"(b[0]), "r"(b[1]));
}
#define CP16(dst, src) \
    asm volatile("cp.async.cg.shared.global [%0], [%1], 16;" \
                 :: "r"((uint32_t)(dst)), "l"(src) : "memory")
#define CP_COMMIT() asm volatile("cp.async.commit_group;" ::: "memory")
#define CP_WAIT(n)  asm volatile("cp.async.wait_group %0;" :: "n"(n) : "memory")

__device__ __forceinline__ void split_h2(float x, float y, __half2& h, __half2& l) {
    h = __float22half2_rn(make_float2(x, y));
    float2 f = __half22float2(h);
    l = __float22half2_rn(make_float2(x - f.x, y - f.y));
}

// ---------------------------------------------------------------------------
// Kernel 0: preconvert X and W to fp16 hi/lo
// ---------------------------------------------------------------------------
#define NX4 2097152   // 8M floats / 4
#define NW4 786432    // 3M floats / 4
__global__ __launch_bounds__(256)
void preconv_kernel(const float* __restrict__ X, const float* __restrict__ W) {
    int idx = blockIdx.x * 256 + threadIdx.x;
    if (idx < NX4) {
        float4 v = ((const float4*)X)[idx];
        __half2 h0, l0, h1, l1;
        split_h2(v.x, v.y, h0, l0);
        split_h2(v.z, v.w, h1, l1);
        *(__half2*)(g_xh + idx * 4)     = h0;
        *(__half2*)(g_xh + idx * 4 + 2) = h1;
        *(__half2*)(g_xl + idx * 4)     = l0;
        *(__half2*)(g_xl + idx * 4 + 2) = l1;
    } else if (idx < NX4 + NW4) {
        int j = idx - NX4;
        float4 v = ((const float4*)W)[j];
        __half2 h0, l0, h1, l1;
        split_h2(v.x, v.y, h0, l0);
        split_h2(v.z, v.w, h1, l1);
        *(__half2*)(g_wh + j * 4)     = h0;
        *(__half2*)(g_wh + j * 4 + 2) = h1;
        *(__half2*)(g_wl + j * 4)     = l0;
        *(__half2*)(g_wl + j * 4 + 2) = l1;
    }
}

// ---------------------------------------------------------------------------
// Kernel 1: QKV GEMM (fp16 hi/lo, 3 passes, all f32 acc), pass-major sweeps.
// 128x128x32 tile, 256 threads (8 warps, 32x64 warp tile), cp.async 2-stage.
// ---------------------------------------------------------------------------
#define ASTRH 40
#define BSTRH 136
#define A_BYTES (128 * ASTRH * 2)   // 10240
#define B_BYTES (32 * BSTRH * 2)    // 8704
#define BUFB (2 * A_BYTES + 2 * B_BYTES)   // 37888

__global__ __launch_bounds__(256)
void qkv_gemm_kernel(const float* __restrict__ bias) {
    extern __shared__ __align__(16) char smem[];

    const int tid = threadIdx.x;
    const int warp = tid >> 5, lane = tid & 31;
    const int g = lane >> 2, tg = lane & 3;
    const int lr = lane & 15;
    const int lc = (lane & 16) >> 1;
    const int wm = (warp & 3) * 32, wn = (warp >> 2) * 64;
    const int bm = blockIdx.y * 128, bn = blockIdx.x * 128;

    float acc[2][8][4];
#pragma unroll
    for (int mt = 0; mt < 2; mt++)
#pragma unroll
        for (int nt = 0; nt < 8; nt++)
#pragma unroll
            for (int i = 0; i < 4; i++) acc[mt][nt][i] = 0.f;

    auto stage = [&](int c, int buf) {
        const int k0 = c * 32;
        uint32_t base = smem_u32(smem) + buf * BUFB;
        uint32_t ah = base, al = base + A_BYTES;
        uint32_t bh = base + 2 * A_BYTES, bl = bh + B_BYTES;
#pragma unroll
        for (int r = 0; r < 2; r++) {
            int l = tid + 256 * r;          // 0..511
            int row = l >> 2, c4 = l & 3;   // A: 128 rows x 4 chunks of 8 halfs
            size_t src = (size_t)(bm + row) * 1024 + k0 + c4 * 8;
            uint32_t d = (uint32_t)(row * ASTRH + c4 * 8) * 2;
            CP16(ah + d, g_xh + src);
            CP16(al + d, g_xl + src);
        }
#pragma unroll
        for (int r = 0; r < 2; r++) {
            int l = tid + 256 * r;
            int row = l >> 4, c16 = l & 15; // B: 32 rows x 16 chunks
            size_t src = (size_t)(k0 + row) * 3072 + bn + c16 * 8;
            uint32_t d = (uint32_t)(row * BSTRH + c16 * 8) * 2;
            CP16(bh + d, g_wh + src);
            CP16(bl + d, g_wl + src);
        }
    };

    stage(0, 0);
    CP_COMMIT();

    for (int c = 0; c < 32; c++) {
        const int buf = c & 1;
        if (c + 1 < 32) {
            stage(c + 1, buf ^ 1);
            CP_COMMIT();
            CP_WAIT(1);
        } else {
            CP_WAIT(0);
        }
        __syncthreads();

        uint32_t base = smem_u32(smem) + buf * BUFB;
        uint32_t ah = base, al = base + A_BYTES;
        uint32_t bh = base + 2 * A_BYTES, bl = bh + B_BYTES;

#pragma unroll
        for (int ks = 0; ks < 2; ks++) {
            int kb = ks * 16;
            // load ALL fragments for this k-step up front
            unsigned ahf[2][4], alf[2][4];
#pragma unroll
            for (int mt = 0; mt < 2; mt++) {
                uint32_t off = (uint32_t)((wm + mt * 16 + lr) * ASTRH + kb + lc) * 2;
                ldm_x4(ahf[mt], ah + off);
                ldm_x4(alf[mt], al + off);
            }
            unsigned bhr[4][4], blr[4][4];
#pragma unroll
            for (int nt2 = 0; nt2 < 4; nt2++) {
                uint32_t off = (uint32_t)((kb + lr) * BSTRH + wn + nt2 * 16 + lc) * 2;
                ldm_x4t(bhr[nt2], bh + off);
                ldm_x4t(blr[nt2], bl + off);
            }
            // pass 1: hi*hi — 16 independent HMMAs (all quads distinct)
#pragma unroll
            for (int nt2 = 0; nt2 < 4; nt2++)
#pragma unroll
                for (int p = 0; p < 2; p++) {
                    unsigned bp[2] = { bhr[nt2][2 * p], bhr[nt2][2 * p + 1] };
#pragma unroll
                    for (int mt = 0; mt < 2; mt++)
                        mma16(acc[mt][nt2 * 2 + p], ahf[mt], bp);
                }
            // pass 2: hi*lo
#pragma unroll
            for (int nt2 = 0; nt2 < 4; nt2++)
#pragma unroll
                for (int p = 0; p < 2; p++) {
                    unsigned bp[2] = { blr[nt2][2 * p], blr[nt2][2 * p + 1] };
#pragma unroll
                    for (int mt = 0; mt < 2; mt++)
                        mma16(acc[mt][nt2 * 2 + p], ahf[mt], bp);
                }
            // pass 3: lo*hi
#pragma unroll
            for (int nt2 = 0; nt2 < 4; nt2++)
#pragma unroll
                for (int p = 0; p < 2; p++) {
                    unsigned bp[2] = { bhr[nt2][2 * p], bhr[nt2][2 * p + 1] };
#pragma unroll
                    for (int mt = 0; mt < 2; mt++)
                        mma16(acc[mt][nt2 * 2 + p], alf[mt], bp);
                }
        }
        __syncthreads();   // all warps done reading before overwrite
    }

    // epilogue: bias + hi/lo split + scatter
#pragma unroll
    for (int nt = 0; nt < 8; nt++) {
        int n0 = bn + wn + nt * 8 + 2 * tg;
        float bia0 = bias[n0], bia1 = bias[n0 + 1];
        int nh  = n0 / 192;
        int rem = n0 - nh * 192;
        int which = rem >> 6;
        int hd = rem & 63;
        __half* ph = (which == 0) ? g_qh : ((which == 1) ? g_kh : g_vh);
        __half* pl = (which == 0) ? g_ql : ((which == 1) ? g_kl : g_vl);
        float sc = (which == 0) ? 8.f : 1.f;
#pragma unroll
        for (int mt = 0; mt < 2; mt++) {
#pragma unroll
            for (int h = 0; h < 2; h++) {
                int m = bm + wm + mt * 16 + g + h * 8;
                int b = m >> 10, s = m & 1023;
                float vx = (acc[mt][nt][h * 2 + 0] + bia0) * sc;
                float vy = (acc[mt][nt][h * 2 + 1] + bia1) * sc;
                __half2 hh, ll;
                split_h2(vx, vy, hh, ll);
                size_t dst = (((size_t)(b * NH_ + nh)) * S_ + s) * HD_ + hd;
                *(__half2*)(ph + dst) = hh;
                *(__half2*)(pl + dst) = ll;
            }
        }
    }
}

// ---------------------------------------------------------------------------
// Kernel 2: fused flash attention. 256 threads (8 warps x 16 queries).
// Pass-major sweeps: QK hh/hl/lh (f32 acc), PV V_hi/V_lo (f32 acc).
// ---------------------------------------------------------------------------
#define QSH 72

__global__ __launch_bounds__(256)
void attn_kernel(const int* __restrict__ mask, float* __restrict__ out) {
    extern __shared__ char smc[];
    __half* Qh = (__half*)smc;          // [128][72]
    __half* Ql = Qh + 128 * QSH;
    __half* Kh = Ql + 128 * QSH;        // [64][72]
    __half* Kl = Kh + 64 * QSH;
    __half* Vh = Kl + 64 * QSH;         // [64][72]
    __half* Vl = Vh + 64 * QSH;
    __half* Ps = Vl + 64 * QSH;         // [128][72]
    int*    mk = (int*)(Ps + 128 * QSH);   // [1024]

    const int bh = blockIdx.y, b = bh >> 4, nh = bh & 15;
    const int q0 = blockIdx.x * 128;
    const int tid = threadIdx.x;
    const int warp = tid >> 5, lane = tid & 31;
    const int g = lane >> 2, tg = lane & 3;
    const int lr = lane & 15;
    const int lc = (lane & 16) >> 1;
    const int wq = warp * 16;

    const unsigned qh_b = smem_u32(Qh), ql_b = smem_u32(Ql);
    const unsigned kh_b = smem_u32(Kh), kl_b = smem_u32(Kl);
    const unsigned vh_b = smem_u32(Vh), vl_b = smem_u32(Vl);
    const unsigned ps_b = smem_u32(Ps);

    // stage Q (pre-scaled) via cp.async + mask
    {
        const size_t qbase = ((size_t)bh * S_ + q0) * HD_;
#pragma unroll
        for (int r = 0; r < 4; r++) {
            int l = tid + 256 * r;          // 0..1023
            int row = l >> 3, c8 = l & 7;   // 128 rows x 8 chunks
            size_t src = qbase + row * 64 + c8 * 8;
            uint32_t d = (uint32_t)(row * QSH + c8 * 8) * 2;
            CP16(qh_b + d, g_qh + src);
            CP16(ql_b + d, g_ql + src);
        }
        CP_COMMIT();
        *(int4*)&mk[tid * 4] = *(const int4*)&mask[b * S_ + tid * 4];
    }

    float O[8][4];
    float mrow[2], lrow[2];
    mrow[0] = -INFINITY; mrow[1] = -INFINITY;
    lrow[0] = 0.f;       lrow[1] = 0.f;
#pragma unroll
    for (int nt = 0; nt < 8; nt++)
#pragma unroll
        for (int i = 0; i < 4; i++) O[nt][i] = 0.f;

    for (int kt = 0; kt < 16; kt++) {
        __syncthreads();   // consumers of previous K/V done
        {
            const size_t kbase = ((size_t)bh * S_ + kt * 64) * HD_;
#pragma unroll
            for (int r = 0; r < 2; r++) {
                int l = tid + 256 * r;          // 0..511
                int row = l >> 3, c8 = l & 7;   // 64 rows x 8 chunks
                size_t src = kbase + row * 64 + c8 * 8;
                uint32_t d = (uint32_t)(row * QSH + c8 * 8) * 2;
                CP16(kh_b + d, g_kh + src);
                CP16(kl_b + d, g_kl + src);
                CP16(vh_b + d, g_vh + src);
                CP16(vl_b + d, g_vl + src);
            }
        }
        CP_COMMIT();
        CP_WAIT(0);
        __syncthreads();

        // ---- S = Q @ K^T (pass-major: hh, hl, lh) ----
        float S[8][4];
#pragma unroll
        for (int nt = 0; nt < 8; nt++)
#pragma unroll
            for (int i = 0; i < 4; i++) S[nt][i] = 0.f;

#pragma unroll
        for (int ks = 0; ks < 4; ks++) {
            int kb = ks * 16;
            unsigned qhf[4], qlf[4];
            {
                uint32_t off = (uint32_t)((wq + lr) * QSH + kb + lc) * 2;
                ldm_x4(qhf, qh_b + off);
                ldm_x4(qlf, ql_b + off);
            }
            unsigned khr[4][4], klr[4][4];
#pragma unroll
            for (int nt2 = 0; nt2 < 4; nt2++) {
                uint32_t off = (uint32_t)((nt2 * 16 + lr) * QSH + kb + lc) * 2;
                ldm_x4(khr[nt2], kh_b + off);
                ldm_x4(klr[nt2], kl_b + off);
            }
            // pass 1: hh — 8 independent HMMAs
#pragma unroll
            for (int nt2 = 0; nt2 < 4; nt2++)
#pragma unroll
                for (int p = 0; p < 2; p++) {
                    unsigned bp[2] = { khr[nt2][p], khr[nt2][p + 2] };
                    mma16(S[nt2 * 2 + p], qhf, bp);
                }
            // pass 2: hl
#pragma unroll
            for (int nt2 = 0; nt2 < 4; nt2++)
#pragma unroll
                for (int p = 0; p < 2; p++) {
                    unsigned bp[2] = { klr[nt2][p], klr[nt2][p + 2] };
                    mma16(S[nt2 * 2 + p], qhf, bp);
                }
            // pass 3: lh
#pragma unroll
            for (int nt2 = 0; nt2 < 4; nt2++)
#pragma unroll
                for (int p = 0; p < 2; p++) {
                    unsigned bp[2] = { khr[nt2][p], khr[nt2][p + 2] };
                    mma16(S[nt2 * 2 + p], qlf, bp);
                }
        }

        // ---- mask ----
#pragma unroll
        for (int nt = 0; nt < 8; nt++) {
            int c = kt * 64 + nt * 8 + 2 * tg;
            if (mk[c])     { S[nt][0] = -10000.f; S[nt][2] = -10000.f; }
            if (mk[c + 1]) { S[nt][1] = -10000.f; S[nt][3] = -10000.f; }
        }

        // ---- online softmax ----
#pragma unroll
        for (int h = 0; h < 2; h++) {
            float rm = -INFINITY;
#pragma unroll
            for (int nt = 0; nt < 8; nt++)
                rm = fmaxf(rm, fmaxf(S[nt][2 * h], S[nt][2 * h + 1]));
            rm = fmaxf(rm, __shfl_xor_sync(0xffffffffu, rm, 1));
            rm = fmaxf(rm, __shfl_xor_sync(0xffffffffu, rm, 2));
            float mn = fmaxf(mrow[h], rm);
            float corr = __expf(mrow[h] - mn);
            mrow[h] = mn;
            float rs = 0.f;
#pragma unroll
            for (int nt = 0; nt < 8; nt++) {
                float e0 = __expf(S[nt][2 * h] - mn);
                float e1 = __expf(S[nt][2 * h + 1] - mn);
                S[nt][2 * h] = e0; S[nt][2 * h + 1] = e1;
                rs += e0 + e1;
            }
            rs += __shfl_xor_sync(0xffffffffu, rs, 1);
            rs += __shfl_xor_sync(0xffffffffu, rs, 2);
            lrow[h] = lrow[h] * corr + rs;
#pragma unroll
            for (int nt = 0; nt < 8; nt++) {
                O[nt][2 * h]     *= corr;
                O[nt][2 * h + 1] *= corr;
            }
        }

        // ---- stash P fp16 (warp-private rows) ----
#pragma unroll
        for (int h = 0; h < 2; h++) {
            int row = wq + g + h * 8;
#pragma unroll
            for (int nt = 0; nt < 8; nt++) {
                __half2 p2 = __float22half2_rn(
                    make_float2(S[nt][2 * h], S[nt][2 * h + 1]));
                *(__half2*)&Ps[row * QSH + nt * 8 + 2 * tg] = p2;
            }
        }
        __syncwarp();

        // ---- O += P @ V (pass-major: V_hi sweep, V_lo sweep) ----
#pragma unroll
        for (int ks = 0; ks < 4; ks++) {
            int kb = ks * 16;
            unsigned pf[4];
            {
                uint32_t off = (uint32_t)((wq + lr) * QSH + kb + lc) * 2;
                ldm_x4(pf, ps_b + off);
            }
            unsigned vhr[4][4], vlr[4][4];
#pragma unroll
            for (int nt2 = 0; nt2 < 4; nt2++) {
                uint32_t off = (uint32_t)((kb + lr) * QSH + nt2 * 16 + lc) * 2;
                ldm_x4t(vhr[nt2], vh_b + off);
                ldm_x4t(vlr[nt2], vl_b + off);
            }
            // pass 1: P * V_hi — 8 independent HMMAs
#pragma unroll
            for (int nt2 = 0; nt2 < 4; nt2++)
#pragma unroll
                for (int p = 0; p < 2; p++) {
                    unsigned bp[2] = { vhr[nt2][2 * p], vhr[nt2][2 * p + 1] };
                    mma16(O[nt2 * 2 + p], pf, bp);
                }
            // pass 2: P * V_lo
#pragma unroll
            for (int nt2 = 0; nt2 < 4; nt2++)
#pragma unroll
                for (int p = 0; p < 2; p++) {
                    unsigned bp[2] = { vlr[nt2][2 * p], vlr[nt2][2 * p + 1] };
                    mma16(O[nt2 * 2 + p], pf, bp);
                }
        }
    }

    // epilogue
#pragma unroll
    for (int h = 0; h < 2; h++) {
        float inv = 1.f / lrow[h];
        int q = q0 + wq + g + h * 8;
        float* op = out + ((size_t)(b * S_ + q)) * H_ + nh * 64;
#pragma unroll
        for (int nt = 0; nt < 8; nt++) {
            float2 v;
            v.x = O[nt][2 * h] * inv;
            v.y = O[nt][2 * h + 1] * inv;
            *(float2*)(op + nt * 8 + 2 * tg) = v;
        }
    }
}

// ---------------------------------------------------------------------------
extern "C" void kernel_launch(void* const* d_in, const int* in_sizes, int n_in,
                              void* d_out, int out_size) {
    const float* hidden = (const float*)d_in[0];   // [8,1024,1024]
    const int*   mask   = (const int*)  d_in[1];   // [8,1,1,1024]
    const float* w_qkv  = (const float*)d_in[2];   // [1024,3072]
    const float* b_qkv  = (const float*)d_in[3];   // [3072]
    float* out = (float*)d_out;

    (void)in_sizes; (void)n_in; (void)out_size;

    // 0: preconvert X, W -> fp16 hi/lo
    int n4 = NX4 + NW4;
    preconv_kernel<<<(n4 + 255) / 256, 256>>>(hidden, w_qkv);

    // 1: QKV GEMM
    size_t smem1 = 2 * (size_t)BUFB;               // 75776
    cudaFuncSetAttribute(qkv_gemm_kernel,
                         cudaFuncAttributeMaxDynamicSharedMemorySize, (int)smem1);
    dim3 g1(3072 / 128, 8192 / 128);               // 24 x 64
    qkv_gemm_kernel<<<g1, 256, smem1>>>(b_qkv);

    // 2: attention
    size_t smem2 = (size_t)(128 * QSH * 3 + 64 * QSH * 4) * sizeof(__half)
                 + 1024 * sizeof(int);             // 96256
    cudaFuncSetAttribute(attn_kernel,
                         cudaFuncAttributeMaxDynamicSharedMemorySize, (int)smem2);
    dim3 g2(S_ / 128, BH_);                         // 8 x 128
    attn_kernel<<<g2, 256, smem2>>>(mask, out);
}

// round 11
// speedup vs baseline: 1.9467x; 1.7040x over previous
#include <cuda_runtime.h>
#include <cuda_fp16.h>
#include <math.h>
#include <stdint.h>

#define B_  8
#define S_  1024
#define H_  1024
#define NH_ 16
#define HD_ 64
#define BH_ (B_*NH_)   // 128

// fp16 hi/lo split scratch (all row-major halfs)
__device__ __half g_xh[(size_t)8192*1024];
__device__ __half g_xl[(size_t)8192*1024];
__device__ __half g_wh[(size_t)1024*3072];
__device__ __half g_wl[(size_t)1024*3072];
__device__ __half g_qh[(size_t)BH_*S_*HD_];   // pre-scaled x8
__device__ __half g_ql[(size_t)BH_*S_*HD_];
__device__ __half g_kh[(size_t)BH_*S_*HD_];
__device__ __half g_kl[(size_t)BH_*S_*HD_];
__device__ __half g_vh[(size_t)BH_*S_*HD_];
__device__ __half g_vl[(size_t)BH_*S_*HD_];
// mask compaction: per-batch active-key lists (padded to 1088) + counts
__device__ int g_cl[8*1088];
__device__ int g_nact[8];

// ---------------------------------------------------------------------------
// helpers
// ---------------------------------------------------------------------------
__device__ __forceinline__ unsigned smem_u32(const void* p) {
    return (unsigned)__cvta_generic_to_shared(p);
}
__device__ __forceinline__ void ldm_x4(unsigned* r, unsigned addr) {
    asm volatile("ldmatrix.sync.aligned.m8n8.x4.shared.b16 {%0,%1,%2,%3}, [%4];"
        : "=r"(r[0]), "=r"(r[1]), "=r"(r[2]), "=r"(r[3]) : "r"(addr));
}
__device__ __forceinline__ void ldm_x4t(unsigned* r, unsigned addr) {
    asm volatile("ldmatrix.sync.aligned.m8n8.x4.trans.shared.b16 {%0,%1,%2,%3}, [%4];"
        : "=r"(r[0]), "=r"(r[1]), "=r"(r[2]), "=r"(r[3]) : "r"(addr));
}
__device__ __forceinline__ void mma16(float* d, const unsigned* a, const unsigned* b) {
    asm volatile(
        "mma.sync.aligned.m16n8k16.row.col.f32.f16.f16.f32 "
        "{%0,%1,%2,%3}, {%4,%5,%6,%7}, {%8,%9}, {%0,%1,%2,%3};\n"
        : "+f"(d[0]), "+f"(d[1]), "+f"(d[2]), "+f"(d[3])
        : "r"(a[0]), "r"(a[1]), "r"(a[2]), "r"(a[3]), "r"(b[0]), "r"(b[1]));
}
#define CP16(dst, src) \
    asm volatile("cp.async.cg.shared.global [%0], [%1], 16;" \
                 :: "r"((uint32_t)(dst)), "l"(src) : "memory")
#define CP_COMMIT() asm volatile("cp.async.commit_group;" ::: "memory")
#define CP_WAIT(n)  asm volatile("cp.async.wait_group %0;" :: "n"(n) : "memory")

__device__ __forceinline__ void split_h2(float x, float y, __half2& h, __half2& l) {
    h = __float22half2_rn(make_float2(x, y));
    float2 f = __half22float2(h);
    l = __float22half2_rn(make_float2(x - f.x, y - f.y));
}

// ---------------------------------------------------------------------------
// Kernel A: per-batch compaction of active keys (mask==0)
// ---------------------------------------------------------------------------
__global__ __launch_bounds__(256)
void compact_kernel(const int* __restrict__ mask) {
    __shared__ int pr[256];
    __shared__ int stot;
    const int b = blockIdx.x, t = threadIdx.x;
    int4 mv = *(const int4*)&mask[b * 1024 + t * 4];
    int loc[4], c = 0;
    if (mv.x == 0) loc[c++] = t * 4 + 0;
    if (mv.y == 0) loc[c++] = t * 4 + 1;
    if (mv.z == 0) loc[c++] = t * 4 + 2;
    if (mv.w == 0) loc[c++] = t * 4 + 3;
    pr[t] = c;
    __syncthreads();
    // inclusive Hillis-Steele scan
    for (int d = 1; d < 256; d <<= 1) {
        int v = pr[t];
        int u = (t >= d) ? pr[t - d] : 0;
        __syncthreads();
        pr[t] = v + u;
        __syncthreads();
    }
    int ofs = pr[t] - c;
    for (int j = 0; j < c; j++) g_cl[b * 1088 + ofs + j] = loc[j];
    if (t == 255) { g_nact[b] = pr[255]; stot = pr[255]; }
    __syncthreads();
    for (int i = stot + t; i < 1088; i += 256) g_cl[b * 1088 + i] = 0;
}

// ---------------------------------------------------------------------------
// Kernel 0: preconvert X and W to fp16 hi/lo
// ---------------------------------------------------------------------------
#define NX4 2097152   // 8M floats / 4
#define NW4 786432    // 3M floats / 4
__global__ __launch_bounds__(256)
void preconv_kernel(const float* __restrict__ X, const float* __restrict__ W) {
    int idx = blockIdx.x * 256 + threadIdx.x;
    if (idx < NX4) {
        float4 v = ((const float4*)X)[idx];
        __half2 h0, l0, h1, l1;
        split_h2(v.x, v.y, h0, l0);
        split_h2(v.z, v.w, h1, l1);
        *(__half2*)(g_xh + idx * 4)     = h0;
        *(__half2*)(g_xh + idx * 4 + 2) = h1;
        *(__half2*)(g_xl + idx * 4)     = l0;
        *(__half2*)(g_xl + idx * 4 + 2) = l1;
    } else if (idx < NX4 + NW4) {
        int j = idx - NX4;
        float4 v = ((const float4*)W)[j];
        __half2 h0, l0, h1, l1;
        split_h2(v.x, v.y, h0, l0);
        split_h2(v.z, v.w, h1, l1);
        *(__half2*)(g_wh + j * 4)     = h0;
        *(__half2*)(g_wh + j * 4 + 2) = h1;
        *(__half2*)(g_wl + j * 4)     = l0;
        *(__half2*)(g_wl + j * 4 + 2) = l1;
    }
}

// ---------------------------------------------------------------------------
// Kernel 1: QKV GEMM, 128m x 64n tiles (each N-tile purely Q, K or V).
// Q-tiles: all rows. K/V-tiles: per-batch compacted active rows (early exit).
// fp16 hi/lo 3 passes, f32 acc, cp.async 2-stage. 8 warps: 4(m) x 2(n).
// ---------------------------------------------------------------------------
#define ASTRH 40
#define BSTR64 72
#define A_BYTES (128 * ASTRH * 2)     // 10240
#define B64_BYTES (32 * BSTR64 * 2)   // 4608
#define BUF2 (2 * A_BYTES + 2 * B64_BYTES)  // 29696

__global__ __launch_bounds__(256)
void qkv_gemm_kernel(const float* __restrict__ bias) {
    extern __shared__ __align__(16) char smem[];
    int* idx = (int*)smem;                 // [128] global row ids
    const uint32_t bufs = smem_u32(smem) + 512;

    const int tid = threadIdx.x;
    const int warp = tid >> 5, lane = tid & 31;
    const int g = lane >> 2, tg = lane & 3;
    const int lr = lane & 15;
    const int lc = (lane & 16) >> 1;
    const int wm = (warp & 3) * 32, wn = (warp >> 2) * 32;
    const int ntn = blockIdx.x;            // 0..47
    const int which = ntn % 3, nh = ntn / 3;
    const int n0 = ntn * 64;

    int nact = 0, lt = 0;
    if (which != 0) {
        int bb = blockIdx.y >> 3;
        lt = blockIdx.y & 7;
        nact = g_nact[bb];
        if (lt * 128 >= nact) return;      // uniform: whole block exits
    }

    if (tid < 128) {
        if (which == 0) idx[tid] = blockIdx.y * 128 + tid;
        else {
            int bb = blockIdx.y >> 3;
            idx[tid] = bb * 1024 + g_cl[bb * 1088 + lt * 128 + tid];
        }
    }
    __syncthreads();

    float acc[2][4][4];
#pragma unroll
    for (int mt = 0; mt < 2; mt++)
#pragma unroll
        for (int nt = 0; nt < 4; nt++)
#pragma unroll
            for (int i = 0; i < 4; i++) acc[mt][nt][i] = 0.f;

    auto stage = [&](int c, int buf) {
        const int k0 = c * 32;
        uint32_t base = bufs + buf * BUF2;
        uint32_t ah = base, al = base + A_BYTES;
        uint32_t bh = base + 2 * A_BYTES, bl = bh + B64_BYTES;
        // A: 128 rows x 32 halfs = 4 chunks/row
#pragma unroll
        for (int r = 0; r < 2; r++) {
            int l = tid + 256 * r;          // 0..511
            int row = l >> 2, c4 = l & 3;
            size_t src = (size_t)idx[row] * 1024 + k0 + c4 * 8;
            uint32_t d = (uint32_t)(row * ASTRH + c4 * 8) * 2;
            CP16(ah + d, g_xh + src);
            CP16(al + d, g_xl + src);
        }
        // B: 32 k-rows x 64 halfs = 8 chunks/row (exactly 256 slots)
        {
            int row = tid >> 3, c8 = tid & 7;
            size_t src = (size_t)(k0 + row) * 3072 + n0 + c8 * 8;
            uint32_t d = (uint32_t)(row * BSTR64 + c8 * 8) * 2;
            CP16(bh + d, g_wh + src);
            CP16(bl + d, g_wl + src);
        }
    };

    stage(0, 0);
    CP_COMMIT();

    for (int c = 0; c < 32; c++) {
        const int buf = c & 1;
        if (c + 1 < 32) {
            stage(c + 1, buf ^ 1);
            CP_COMMIT();
            CP_WAIT(1);
        } else {
            CP_WAIT(0);
        }
        __syncthreads();

        uint32_t base = bufs + buf * BUF2;
        uint32_t ah = base, al = base + A_BYTES;
        uint32_t bh = base + 2 * A_BYTES, bl = bh + B64_BYTES;

#pragma unroll
        for (int ks = 0; ks < 2; ks++) {
            int kb = ks * 16;
            unsigned ahf[2][4], alf[2][4];
#pragma unroll
            for (int mt = 0; mt < 2; mt++) {
                uint32_t off = (uint32_t)((wm + mt * 16 + lr) * ASTRH + kb + lc) * 2;
                ldm_x4(ahf[mt], ah + off);
                ldm_x4(alf[mt], al + off);
            }
#pragma unroll
            for (int nt2 = 0; nt2 < 2; nt2++) {
                uint32_t off = (uint32_t)((kb + lr) * BSTR64 + wn + nt2 * 16 + lc) * 2;
                unsigned bhr[4], blr[4];
                ldm_x4t(bhr, bh + off);
                ldm_x4t(blr, bl + off);
#pragma unroll
                for (int p = 0; p < 2; p++) {
                    int nt = nt2 * 2 + p;
                    unsigned bhp[2] = { bhr[2 * p], bhr[2 * p + 1] };
                    unsigned blp[2] = { blr[2 * p], blr[2 * p + 1] };
#pragma unroll
                    for (int mt = 0; mt < 2; mt++) {
                        mma16(acc[mt][nt], ahf[mt], bhp);   // hi*hi
                        mma16(acc[mt][nt], ahf[mt], blp);   // hi*lo
                        mma16(acc[mt][nt], alf[mt], bhp);   // lo*hi
                    }
                }
            }
        }
        __syncthreads();
    }

    // epilogue: bias + hi/lo split + scatter (predicated for padded kv rows)
    __half* ph = (which == 0) ? g_qh : ((which == 1) ? g_kh : g_vh);
    __half* pl = (which == 0) ? g_ql : ((which == 1) ? g_kl : g_vl);
    const float sc = (which == 0) ? 8.f : 1.f;
#pragma unroll
    for (int nt = 0; nt < 4; nt++) {
        int n = n0 + wn + nt * 8 + 2 * tg;
        float bia0 = bias[n], bia1 = bias[n + 1];
        int hd = n - nh * 192 - which * 64;
#pragma unroll
        for (int mt = 0; mt < 2; mt++) {
#pragma unroll
            for (int h = 0; h < 2; h++) {
                int rit = wm + mt * 16 + g + h * 8;
                if (which != 0 && lt * 128 + rit >= nact) continue;
                int m = idx[rit];
                int b = m >> 10, s = m & 1023;
                float vx = (acc[mt][nt][h * 2 + 0] + bia0) * sc;
                float vy = (acc[mt][nt][h * 2 + 1] + bia1) * sc;
                __half2 hh, ll;
                split_h2(vx, vy, hh, ll);
                size_t dst = (((size_t)(b * NH_ + nh)) * S_ + s) * HD_ + hd;
                *(__half2*)(ph + dst) = hh;
                *(__half2*)(pl + dst) = ll;
            }
        }
    }
}

// ---------------------------------------------------------------------------
// Kernel 2: fused flash attention over COMPACTED keys.
// 256 threads (8 warps x 16 queries), 128-query tile, dynamic key-tiles of 64.
// ---------------------------------------------------------------------------
#define QSH 72

__global__ __launch_bounds__(256)
void attn_kernel(float* __restrict__ out) {
    extern __shared__ char smc[];
    __half* Qh = (__half*)smc;          // [128][72]
    __half* Ql = Qh + 128 * QSH;
    __half* Kh = Ql + 128 * QSH;        // [64][72]
    __half* Kl = Kh + 64 * QSH;
    __half* Vh = Kl + 64 * QSH;         // [64][72]
    __half* Vl = Vh + 64 * QSH;
    __half* Ps = Vl + 64 * QSH;         // [128][72]

    const int bh = blockIdx.y, b = bh >> 4, nh = bh & 15;
    const int q0 = blockIdx.x * 128;
    const int tid = threadIdx.x;
    const int warp = tid >> 5, lane = tid & 31;
    const int g = lane >> 2, tg = lane & 3;
    const int lr = lane & 15;
    const int lc = (lane & 16) >> 1;
    const int wq = warp * 16;

    const unsigned qh_b = smem_u32(Qh), ql_b = smem_u32(Ql);
    const unsigned kh_b = smem_u32(Kh), kl_b = smem_u32(Kl);
    const unsigned vh_b = smem_u32(Vh), vl_b = smem_u32(Vl);
    const unsigned ps_b = smem_u32(Ps);

    const int nact = g_nact[b];
    const int ktiles = (nact + 63) >> 6;
    const int* cl = g_cl + b * 1088;

    // stage Q (pre-scaled) via cp.async
    {
        const size_t qbase = ((size_t)bh * S_ + q0) * HD_;
#pragma unroll
        for (int r = 0; r < 4; r++) {
            int l = tid + 256 * r;          // 0..1023
            int row = l >> 3, c8 = l & 7;   // 128 rows x 8 chunks
            size_t src = qbase + row * 64 + c8 * 8;
            uint32_t d = (uint32_t)(row * QSH + c8 * 8) * 2;
            CP16(qh_b + d, g_qh + src);
            CP16(ql_b + d, g_ql + src);
        }
        CP_COMMIT();
    }

    float O[8][4];
    float mrow[2], lrow[2];
    mrow[0] = -INFINITY; mrow[1] = -INFINITY;
    lrow[0] = 0.f;       lrow[1] = 0.f;
#pragma unroll
    for (int nt = 0; nt < 8; nt++)
#pragma unroll
        for (int i = 0; i < 4; i++) O[nt][i] = 0.f;

    for (int kt = 0; kt < ktiles; kt++) {
        __syncthreads();   // consumers of previous K/V done
        {
#pragma unroll
            for (int r = 0; r < 2; r++) {
                int l = tid + 256 * r;          // 0..511
                int row = l >> 3, c8 = l & 7;   // 64 rows x 8 chunks
                int s_idx = cl[kt * 64 + row];  // compacted key -> original s
                size_t src = ((size_t)bh * S_ + s_idx) * HD_ + c8 * 8;
                uint32_t d = (uint32_t)(row * QSH + c8 * 8) * 2;
                CP16(kh_b + d, g_kh + src);
                CP16(kl_b + d, g_kl + src);
                CP16(vh_b + d, g_vh + src);
                CP16(vl_b + d, g_vl + src);
            }
        }
        CP_COMMIT();
        CP_WAIT(0);
        __syncthreads();

        // ---- S = Q @ K^T (hh, hl, lh interleaved per nt) ----
        float S[8][4];
#pragma unroll
        for (int nt = 0; nt < 8; nt++)
#pragma unroll
            for (int i = 0; i < 4; i++) S[nt][i] = 0.f;

#pragma unroll
        for (int ks = 0; ks < 4; ks++) {
            int kb = ks * 16;
            unsigned qhf[4], qlf[4];
            {
                uint32_t off = (uint32_t)((wq + lr) * QSH + kb + lc) * 2;
                ldm_x4(qhf, qh_b + off);
                ldm_x4(qlf, ql_b + off);
            }
#pragma unroll
            for (int nt2 = 0; nt2 < 4; nt2++) {
                uint32_t off = (uint32_t)((nt2 * 16 + lr) * QSH + kb + lc) * 2;
                unsigned khr[4], klr[4];
                ldm_x4(khr, kh_b + off);
                ldm_x4(klr, kl_b + off);
#pragma unroll
                for (int p = 0; p < 2; p++) {
                    int nt = nt2 * 2 + p;
                    unsigned bhp[2] = { khr[p], khr[p + 2] };
                    unsigned blp[2] = { klr[p], klr[p + 2] };
                    mma16(S[nt], qhf, bhp);
                    mma16(S[nt], qhf, blp);
                    mma16(S[nt], qlf, bhp);
                }
            }
        }

        // ---- partial-tile mask: compacted col >= nact -> -10000 ----
        int rem = nact - kt * 64;
        if (rem < 64) {
#pragma unroll
            for (int nt = 0; nt < 8; nt++) {
                int c = nt * 8 + 2 * tg;
                if (c >= rem)     { S[nt][0] = -10000.f; S[nt][2] = -10000.f; }
                if (c + 1 >= rem) { S[nt][1] = -10000.f; S[nt][3] = -10000.f; }
            }
        }

        // ---- online softmax ----
#pragma unroll
        for (int h = 0; h < 2; h++) {
            float rm = -INFINITY;
#pragma unroll
            for (int nt = 0; nt < 8; nt++)
                rm = fmaxf(rm, fmaxf(S[nt][2 * h], S[nt][2 * h + 1]));
            rm = fmaxf(rm, __shfl_xor_sync(0xffffffffu, rm, 1));
            rm = fmaxf(rm, __shfl_xor_sync(0xffffffffu, rm, 2));
            float mn = fmaxf(mrow[h], rm);
            float corr = __expf(mrow[h] - mn);
            mrow[h] = mn;
            float rs = 0.f;
#pragma unroll
            for (int nt = 0; nt < 8; nt++) {
                float e0 = __expf(S[nt][2 * h] - mn);
                float e1 = __expf(S[nt][2 * h + 1] - mn);
                S[nt][2 * h] = e0; S[nt][2 * h + 1] = e1;
                rs += e0 + e1;
            }
            rs += __shfl_xor_sync(0xffffffffu, rs, 1);
            rs += __shfl_xor_sync(0xffffffffu, rs, 2);
            lrow[h] = lrow[h] * corr + rs;
#pragma unroll
            for (int nt = 0; nt < 8; nt++) {
                O[nt][2 * h]     *= corr;
                O[nt][2 * h + 1] *= corr;
            }
        }

        // ---- stash P fp16 (warp-private rows) ----
#pragma unroll
        for (int h = 0; h < 2; h++) {
            int row = wq + g + h * 8;
#pragma unroll
            for (int nt = 0; nt < 8; nt++) {
                __half2 p2 = __float22half2_rn(
                    make_float2(S[nt][2 * h], S[nt][2 * h + 1]));
                *(__half2*)&Ps[row * QSH + nt * 8 + 2 * tg] = p2;
            }
        }
        __syncwarp();

        // ---- O += P @ V (V_hi then V_lo per nt) ----
#pragma unroll
        for (int ks = 0; ks < 4; ks++) {
            int kb = ks * 16;
            unsigned pf[4];
            {
                uint32_t off = (uint32_t)((wq + lr) * QSH + kb + lc) * 2;
                ldm_x4(pf, ps_b + off);
            }
#pragma unroll
            for (int nt2 = 0; nt2 < 4; nt2++) {
                uint32_t off = (uint32_t)((kb + lr) * QSH + nt2 * 16 + lc) * 2;
                unsigned vhr[4], vlr[4];
                ldm_x4t(vhr, vh_b + off);
                ldm_x4t(vlr, vl_b + off);
#pragma unroll
                for (int p = 0; p < 2; p++) {
                    int nt = nt2 * 2 + p;
                    unsigned bhp[2] = { vhr[2 * p], vhr[2 * p + 1] };
                    unsigned blp[2] = { vlr[2 * p], vlr[2 * p + 1] };
                    mma16(O[nt], pf, bhp);
                    mma16(O[nt], pf, blp);
                }
            }
        }
    }

    // epilogue
#pragma unroll
    for (int h = 0; h < 2; h++) {
        float inv = 1.f / lrow[h];
        int q = q0 + wq + g + h * 8;
        float* op = out + ((size_t)(b * S_ + q)) * H_ + nh * 64;
#pragma unroll
        for (int nt = 0; nt < 8; nt++) {
            float2 v;
            v.x = O[nt][2 * h] * inv;
            v.y = O[nt][2 * h + 1] * inv;
            *(float2*)(op + nt * 8 + 2 * tg) = v;
        }
    }
}

// ---------------------------------------------------------------------------
extern "C" void kernel_launch(void* const* d_in, const int* in_sizes, int n_in,
                              void* d_out, int out_size) {
    const float* hidden = (const float*)d_in[0];   // [8,1024,1024]
    const int*   mask   = (const int*)  d_in[1];   // [8,1,1,1024]
    const float* w_qkv  = (const float*)d_in[2];   // [1024,3072]
    const float* b_qkv  = (const float*)d_in[3];   // [3072]
    float* out = (float*)d_out;

    (void)in_sizes; (void)n_in; (void)out_size;

    // A: build per-batch active-key lists
    compact_kernel<<<8, 256>>>(mask);

    // 0: preconvert X, W -> fp16 hi/lo
    int n4 = NX4 + NW4;
    preconv_kernel<<<(n4 + 255) / 256, 256>>>(hidden, w_qkv);

    // 1: QKV GEMM (64-wide N tiles; K/V tiles use compacted rows)
    size_t smem1 = 512 + 2 * (size_t)BUF2;         // 59904
    cudaFuncSetAttribute(qkv_gemm_kernel,
                         cudaFuncAttributeMaxDynamicSharedMemorySize, (int)smem1);
    dim3 g1(48, 64);
    qkv_gemm_kernel<<<g1, 256, smem1>>>(b_qkv);

    // 2: attention over compacted keys
    size_t smem2 = (size_t)(128 * QSH * 3 + 64 * QSH * 4) * sizeof(__half); // 92160
    cudaFuncSetAttribute(attn_kernel,
                         cudaFuncAttributeMaxDynamicSharedMemorySize, (int)smem2);
    dim3 g2(S_ / 128, BH_);                         // 8 x 128
    attn_kernel<<<g2, 256, smem2>>>(out);
}

// round 13
// speedup vs baseline: 2.0920x; 1.0746x over previous
#include <cuda_runtime.h>
#include <cuda_fp16.h>
#include <math.h>
#include <stdint.h>

#define B_  8
#define S_  1024
#define H_  1024
#define NH_ 16
#define HD_ 64
#define BH_ (B_*NH_)   // 128

// fp16 hi/lo split scratch (all row-major halfs)
__device__ __half g_xh[(size_t)8192*1024];
__device__ __half g_xl[(size_t)8192*1024];
__device__ __half g_wh[(size_t)1024*3072];
__device__ __half g_wl[(size_t)1024*3072];
__device__ __half g_qh[(size_t)BH_*S_*HD_];   // pre-scaled x8
__device__ __half g_ql[(size_t)BH_*S_*HD_];
__device__ __half g_kh[(size_t)BH_*S_*HD_];
__device__ __half g_kl[(size_t)BH_*S_*HD_];
__device__ __half g_vh[(size_t)BH_*S_*HD_];   // single fp16 (rounded)
// mask compaction: per-batch active-key lists (padded to 1088) + counts
__device__ int g_cl[8*1088];
__device__ int g_nact[8];

// ---------------------------------------------------------------------------
// helpers
// ---------------------------------------------------------------------------
__device__ __forceinline__ unsigned smem_u32(const void* p) {
    return (unsigned)__cvta_generic_to_shared(p);
}
__device__ __forceinline__ void ldm_x4(unsigned* r, unsigned addr) {
    asm volatile("ldmatrix.sync.aligned.m8n8.x4.shared.b16 {%0,%1,%2,%3}, [%4];"
        : "=r"(r[0]), "=r"(r[1]), "=r"(r[2]), "=r"(r[3]) : "r"(addr));
}
__device__ __forceinline__ void ldm_x4t(unsigned* r, unsigned addr) {
    asm volatile("ldmatrix.sync.aligned.m8n8.x4.trans.shared.b16 {%0,%1,%2,%3}, [%4];"
        : "=r"(r[0]), "=r"(r[1]), "=r"(r[2]), "=r"(r[3]) : "r"(addr));
}
__device__ __forceinline__ void mma16(float* d, const unsigned* a, const unsigned* b) {
    asm volatile(
        "mma.sync.aligned.m16n8k16.row.col.f32.f16.f16.f32 "
        "{%0,%1,%2,%3}, {%4,%5,%6,%7}, {%8,%9}, {%0,%1,%2,%3};\n"
        : "+f"(d[0]), "+f"(d[1]), "+f"(d[2]), "+f"(d[3])
        : "r"(a[0]), "r"(a[1]), "r"(a[2]), "r"(a[3]), "r"(b[0]), "r"(b[1]));
}
#define CP16(dst, src) \
    asm volatile("cp.async.cg.shared.global [%0], [%1], 16;" \
                 :: "r"((uint32_t)(dst)), "l"(src) : "memory")
#define CP_COMMIT() asm volatile("cp.async.commit_group;" ::: "memory")
#define CP_WAIT(n)  asm volatile("cp.async.wait_group %0;" :: "n"(n) : "memory")

__device__ __forceinline__ void split_h2(float x, float y, __half2& h, __half2& l) {
    h = __float22half2_rn(make_float2(x, y));
    float2 f = __half22float2(h);
    l = __float22half2_rn(make_float2(x - f.x, y - f.y));
}
__device__ __forceinline__ unsigned pack_h2(float x, float y) {
    __half2 h = __float22half2_rn(make_float2(x, y));
    unsigned u;
    memcpy(&u, &h, 4);
    return u;
}

// ---------------------------------------------------------------------------
// Kernel A: per-batch compaction of active keys (mask==0)
// ---------------------------------------------------------------------------
__global__ __launch_bounds__(256)
void compact_kernel(const int* __restrict__ mask) {
    __shared__ int pr[256];
    __shared__ int stot;
    const int b = blockIdx.x, t = threadIdx.x;
    int4 mv = *(const int4*)&mask[b * 1024 + t * 4];
    int loc[4], c = 0;
    if (mv.x == 0) loc[c++] = t * 4 + 0;
    if (mv.y == 0) loc[c++] = t * 4 + 1;
    if (mv.z == 0) loc[c++] = t * 4 + 2;
    if (mv.w == 0) loc[c++] = t * 4 + 3;
    pr[t] = c;
    __syncthreads();
    for (int d = 1; d < 256; d <<= 1) {
        int v = pr[t];
        int u = (t >= d) ? pr[t - d] : 0;
        __syncthreads();
        pr[t] = v + u;
        __syncthreads();
    }
    int ofs = pr[t] - c;
    for (int j = 0; j < c; j++) g_cl[b * 1088 + ofs + j] = loc[j];
    if (t == 255) { g_nact[b] = pr[255]; stot = pr[255]; }
    __syncthreads();
    for (int i = stot + t; i < 1088; i += 256) g_cl[b * 1088 + i] = 0;
}

// ---------------------------------------------------------------------------
// Kernel 0: preconvert X and W to fp16 hi/lo
// ---------------------------------------------------------------------------
#define NX4 2097152
#define NW4 786432
__global__ __launch_bounds__(256)
void preconv_kernel(const float* __restrict__ X, const float* __restrict__ W) {
    int idx = blockIdx.x * 256 + threadIdx.x;
    if (idx < NX4) {
        float4 v = ((const float4*)X)[idx];
        __half2 h0, l0, h1, l1;
        split_h2(v.x, v.y, h0, l0);
        split_h2(v.z, v.w, h1, l1);
        *(__half2*)(g_xh + idx * 4)     = h0;
        *(__half2*)(g_xh + idx * 4 + 2) = h1;
        *(__half2*)(g_xl + idx * 4)     = l0;
        *(__half2*)(g_xl + idx * 4 + 2) = l1;
    } else if (idx < NX4 + NW4) {
        int j = idx - NX4;
        float4 v = ((const float4*)W)[j];
        __half2 h0, l0, h1, l1;
        split_h2(v.x, v.y, h0, l0);
        split_h2(v.z, v.w, h1, l1);
        *(__half2*)(g_wh + j * 4)     = h0;
        *(__half2*)(g_wh + j * 4 + 2) = h1;
        *(__half2*)(g_wl + j * 4)     = l0;
        *(__half2*)(g_wl + j * 4 + 2) = l1;
    }
}

// ---------------------------------------------------------------------------
// Kernel 1: QKV GEMM, 128m x 64n tiles (each N-tile purely Q, K or V).
// Q/K-tiles: 3 passes. V-tiles: 2 passes (hh+hl), single fp16 output.
// ---------------------------------------------------------------------------
#define ASTRH 40
#define BSTR64 72
#define A_BYTES (128 * ASTRH * 2)     // 10240
#define B64_BYTES (32 * BSTR64 * 2)   // 4608
#define BUF2 (2 * A_BYTES + 2 * B64_BYTES)  // 29696

__global__ __launch_bounds__(256)
void qkv_gemm_kernel(const float* __restrict__ bias) {
    extern __shared__ __align__(16) char smem[];
    int* idx = (int*)smem;                 // [128] global row ids
    const uint32_t bufs = smem_u32(smem) + 512;

    const int tid = threadIdx.x;
    const int warp = tid >> 5, lane = tid & 31;
    const int g = lane >> 2, tg = lane & 3;
    const int lr = lane & 15;
    const int lc = (lane & 16) >> 1;
    const int wm = (warp & 3) * 32, wn = (warp >> 2) * 32;
    const int ntn = blockIdx.x;            // 0..47
    const int which = ntn % 3, nh = ntn / 3;
    const int n0 = ntn * 64;
    const bool do_lh = (which != 2);       // V skips lo*hi pass

    int nact = 0, lt = 0;
    if (which != 0) {
        int bb = blockIdx.y >> 3;
        lt = blockIdx.y & 7;
        nact = g_nact[bb];
        if (lt * 128 >= nact) return;
    }

    if (tid < 128) {
        if (which == 0) idx[tid] = blockIdx.y * 128 + tid;
        else {
            int bb = blockIdx.y >> 3;
            idx[tid] = bb * 1024 + g_cl[bb * 1088 + lt * 128 + tid];
        }
    }
    __syncthreads();

    float acc[2][4][4];
#pragma unroll
    for (int mt = 0; mt < 2; mt++)
#pragma unroll
        for (int nt = 0; nt < 4; nt++)
#pragma unroll
            for (int i = 0; i < 4; i++) acc[mt][nt][i] = 0.f;

    auto stage = [&](int c, int buf) {
        const int k0 = c * 32;
        uint32_t base = bufs + buf * BUF2;
        uint32_t ah = base, al = base + A_BYTES;
        uint32_t bh = base + 2 * A_BYTES, bl = bh + B64_BYTES;
#pragma unroll
        for (int r = 0; r < 2; r++) {
            int l = tid + 256 * r;
            int row = l >> 2, c4 = l & 3;
            size_t src = (size_t)idx[row] * 1024 + k0 + c4 * 8;
            uint32_t d = (uint32_t)(row * ASTRH + c4 * 8) * 2;
            CP16(ah + d, g_xh + src);
            CP16(al + d, g_xl + src);
        }
        {
            int row = tid >> 3, c8 = tid & 7;
            size_t src = (size_t)(k0 + row) * 3072 + n0 + c8 * 8;
            uint32_t d = (uint32_t)(row * BSTR64 + c8 * 8) * 2;
            CP16(bh + d, g_wh + src);
            CP16(bl + d, g_wl + src);
        }
    };

    stage(0, 0);
    CP_COMMIT();

    for (int c = 0; c < 32; c++) {
        const int buf = c & 1;
        if (c + 1 < 32) {
            stage(c + 1, buf ^ 1);
            CP_COMMIT();
            CP_WAIT(1);
        } else {
            CP_WAIT(0);
        }
        __syncthreads();

        uint32_t base = bufs + buf * BUF2;
        uint32_t ah = base, al = base + A_BYTES;
        uint32_t bh = base + 2 * A_BYTES, bl = bh + B64_BYTES;

#pragma unroll
        for (int ks = 0; ks < 2; ks++) {
            int kb = ks * 16;
            unsigned ahf[2][4], alf[2][4];
#pragma unroll
            for (int mt = 0; mt < 2; mt++) {
                uint32_t off = (uint32_t)((wm + mt * 16 + lr) * ASTRH + kb + lc) * 2;
                ldm_x4(ahf[mt], ah + off);
                ldm_x4(alf[mt], al + off);
            }
#pragma unroll
            for (int nt2 = 0; nt2 < 2; nt2++) {
                uint32_t off = (uint32_t)((kb + lr) * BSTR64 + wn + nt2 * 16 + lc) * 2;
                unsigned bhr[4], blr[4];
                ldm_x4t(bhr, bh + off);
                ldm_x4t(blr, bl + off);
#pragma unroll
                for (int p = 0; p < 2; p++) {
                    int nt = nt2 * 2 + p;
                    unsigned bhp[2] = { bhr[2 * p], bhr[2 * p + 1] };
                    unsigned blp[2] = { blr[2 * p], blr[2 * p + 1] };
#pragma unroll
                    for (int mt = 0; mt < 2; mt++) {
                        mma16(acc[mt][nt], ahf[mt], bhp);               // hi*hi
                        mma16(acc[mt][nt], ahf[mt], blp);               // hi*lo
                        if (do_lh) mma16(acc[mt][nt], alf[mt], bhp);    // lo*hi
                    }
                }
            }
        }
        __syncthreads();
    }

    // epilogue
    const float sc = (which == 0) ? 8.f : 1.f;
#pragma unroll
    for (int nt = 0; nt < 4; nt++) {
        int n = n0 + wn + nt * 8 + 2 * tg;
        float bia0 = bias[n], bia1 = bias[n + 1];
        int hd = n - nh * 192 - which * 64;
#pragma unroll
        for (int mt = 0; mt < 2; mt++) {
#pragma unroll
            for (int h = 0; h < 2; h++) {
                int rit = wm + mt * 16 + g + h * 8;
                if (which != 0 && lt * 128 + rit >= nact) continue;
                int m = idx[rit];
                int b = m >> 10, s = m & 1023;
                float vx = (acc[mt][nt][h * 2 + 0] + bia0) * sc;
                float vy = (acc[mt][nt][h * 2 + 1] + bia1) * sc;
                size_t dst = (((size_t)(b * NH_ + nh)) * S_ + s) * HD_ + hd;
                if (which == 2) {
                    *(__half2*)(g_vh + dst) =
                        __float22half2_rn(make_float2(vx, vy));
                } else {
                    __half2 hh, ll;
                    split_h2(vx, vy, hh, ll);
                    __half* ph = (which == 0) ? g_qh : g_kh;
                    __half* pl = (which == 0) ? g_ql : g_kl;
                    *(__half2*)(ph + dst) = hh;
                    *(__half2*)(pl + dst) = ll;
                }
            }
        }
    }
}

// ---------------------------------------------------------------------------
// Kernel 2: fused flash attention over COMPACTED keys.
// QK 3 passes; PV SINGLE pass with register-resident P (C-frag -> A-frag).
// ---------------------------------------------------------------------------
#define QSH 72

__global__ __launch_bounds__(256)
void attn_kernel(float* __restrict__ out) {
    extern __shared__ char smc[];
    __half* Qh = (__half*)smc;          // [128][72]
    __half* Ql = Qh + 128 * QSH;
    __half* Kh = Ql + 128 * QSH;        // [64][72]
    __half* Kl = Kh + 64 * QSH;
    __half* Vh = Kl + 64 * QSH;         // [64][72] single fp16

    const int bh = blockIdx.y, b = bh >> 4, nh = bh & 15;
    const int q0 = blockIdx.x * 128;
    const int tid = threadIdx.x;
    const int warp = tid >> 5, lane = tid & 31;
    const int g = lane >> 2, tg = lane & 3;
    const int lr = lane & 15;
    const int lc = (lane & 16) >> 1;
    const int wq = warp * 16;

    const unsigned qh_b = smem_u32(Qh), ql_b = smem_u32(Ql);
    const unsigned kh_b = smem_u32(Kh), kl_b = smem_u32(Kl);
    const unsigned vh_b = smem_u32(Vh);

    const int nact = g_nact[b];
    const int ktiles = (nact + 63) >> 6;
    const int* cl = g_cl + b * 1088;

    // stage Q (pre-scaled) via cp.async
    {
        const size_t qbase = ((size_t)bh * S_ + q0) * HD_;
#pragma unroll
        for (int r = 0; r < 4; r++) {
            int l = tid + 256 * r;
            int row = l >> 3, c8 = l & 7;
            size_t src = qbase + row * 64 + c8 * 8;
            uint32_t d = (uint32_t)(row * QSH + c8 * 8) * 2;
            CP16(qh_b + d, g_qh + src);
            CP16(ql_b + d, g_ql + src);
        }
        CP_COMMIT();
    }

    float O[8][4];
    float mrow[2], lrow[2];
    mrow[0] = -INFINITY; mrow[1] = -INFINITY;
    lrow[0] = 0.f;       lrow[1] = 0.f;
#pragma unroll
    for (int nt = 0; nt < 8; nt++)
#pragma unroll
        for (int i = 0; i < 4; i++) O[nt][i] = 0.f;

    for (int kt = 0; kt < ktiles; kt++) {
        __syncthreads();
        {
#pragma unroll
            for (int r = 0; r < 2; r++) {
                int l = tid + 256 * r;
                int row = l >> 3, c8 = l & 7;
                int s_idx = cl[kt * 64 + row];
                size_t src = ((size_t)bh * S_ + s_idx) * HD_ + c8 * 8;
                uint32_t d = (uint32_t)(row * QSH + c8 * 8) * 2;
                CP16(kh_b + d, g_kh + src);
                CP16(kl_b + d, g_kl + src);
                CP16(vh_b + d, g_vh + src);
            }
        }
        CP_COMMIT();
        CP_WAIT(0);
        __syncthreads();

        // ---- S = Q @ K^T (hh, hl, lh) ----
        float S[8][4];
#pragma unroll
        for (int nt = 0; nt < 8; nt++)
#pragma unroll
            for (int i = 0; i < 4; i++) S[nt][i] = 0.f;

#pragma unroll
        for (int ks = 0; ks < 4; ks++) {
            int kb = ks * 16;
            unsigned qhf[4], qlf[4];
            {
                uint32_t off = (uint32_t)((wq + lr) * QSH + kb + lc) * 2;
                ldm_x4(qhf, qh_b + off);
                ldm_x4(qlf, ql_b + off);
            }
#pragma unroll
            for (int nt2 = 0; nt2 < 4; nt2++) {
                uint32_t off = (uint32_t)((nt2 * 16 + lr) * QSH + kb + lc) * 2;
                unsigned khr[4], klr[4];
                ldm_x4(khr, kh_b + off);
                ldm_x4(klr, kl_b + off);
#pragma unroll
                for (int p = 0; p < 2; p++) {
                    int nt = nt2 * 2 + p;
                    unsigned bhp[2] = { khr[p], khr[p + 2] };
                    unsigned blp[2] = { klr[p], klr[p + 2] };
                    mma16(S[nt], qhf, bhp);
                    mma16(S[nt], qhf, blp);
                    mma16(S[nt], qlf, bhp);
                }
            }
        }

        // ---- partial-tile mask: compacted col >= nact -> -10000 ----
        int rem = nact - kt * 64;
        if (rem < 64) {
#pragma unroll
            for (int nt = 0; nt < 8; nt++) {
                int c = nt * 8 + 2 * tg;
                if (c >= rem)     { S[nt][0] = -10000.f; S[nt][2] = -10000.f; }
                if (c + 1 >= rem) { S[nt][1] = -10000.f; S[nt][3] = -10000.f; }
            }
        }

        // ---- online softmax ----
#pragma unroll
        for (int h = 0; h < 2; h++) {
            float rm = -INFINITY;
#pragma unroll
            for (int nt = 0; nt < 8; nt++)
                rm = fmaxf(rm, fmaxf(S[nt][2 * h], S[nt][2 * h + 1]));
            rm = fmaxf(rm, __shfl_xor_sync(0xffffffffu, rm, 1));
            rm = fmaxf(rm, __shfl_xor_sync(0xffffffffu, rm, 2));
            float mn = fmaxf(mrow[h], rm);
            float corr = __expf(mrow[h] - mn);
            mrow[h] = mn;
            float rs = 0.f;
#pragma unroll
            for (int nt = 0; nt < 8; nt++) {
                float e0 = __expf(S[nt][2 * h] - mn);
                float e1 = __expf(S[nt][2 * h + 1] - mn);
                S[nt][2 * h] = e0; S[nt][2 * h + 1] = e1;
                rs += e0 + e1;
            }
            rs += __shfl_xor_sync(0xffffffffu, rs, 1);
            rs += __shfl_xor_sync(0xffffffffu, rs, 2);
            lrow[h] = lrow[h] * corr + rs;
#pragma unroll
            for (int nt = 0; nt < 8; nt++) {
                O[nt][2 * h]     *= corr;
                O[nt][2 * h + 1] *= corr;
            }
        }

        // ---- build P A-fragments in registers (C-frag -> A-frag identity) ----
        unsigned pf[4][4];
#pragma unroll
        for (int kc = 0; kc < 4; kc++) {
            pf[kc][0] = pack_h2(S[2 * kc][0],     S[2 * kc][1]);
            pf[kc][1] = pack_h2(S[2 * kc][2],     S[2 * kc][3]);
            pf[kc][2] = pack_h2(S[2 * kc + 1][0], S[2 * kc + 1][1]);
            pf[kc][3] = pack_h2(S[2 * kc + 1][2], S[2 * kc + 1][3]);
        }

        // ---- O += P @ V (single pass) ----
#pragma unroll
        for (int kc = 0; kc < 4; kc++) {
            int kb = kc * 16;
#pragma unroll
            for (int nt2 = 0; nt2 < 4; nt2++) {
                uint32_t off = (uint32_t)((kb + lr) * QSH + nt2 * 16 + lc) * 2;
                unsigned vhr[4];
                ldm_x4t(vhr, vh_b + off);
#pragma unroll
                for (int p = 0; p < 2; p++) {
                    unsigned bp[2] = { vhr[2 * p], vhr[2 * p + 1] };
                    mma16(O[nt2 * 2 + p], pf[kc], bp);
                }
            }
        }
    }

    // epilogue
#pragma unroll
    for (int h = 0; h < 2; h++) {
        float inv = 1.f / lrow[h];
        int q = q0 + wq + g + h * 8;
        float* op = out + ((size_t)(b * S_ + q)) * H_ + nh * 64;
#pragma unroll
        for (int nt = 0; nt < 8; nt++) {
            float2 v;
            v.x = O[nt][2 * h] * inv;
            v.y = O[nt][2 * h + 1] * inv;
            *(float2*)(op + nt * 8 + 2 * tg) = v;
        }
    }
}

// ---------------------------------------------------------------------------
extern "C" void kernel_launch(void* const* d_in, const int* in_sizes, int n_in,
                              void* d_out, int out_size) {
    const float* hidden = (const float*)d_in[0];   // [8,1024,1024]
    const int*   mask   = (const int*)  d_in[1];   // [8,1,1,1024]
    const float* w_qkv  = (const float*)d_in[2];   // [1024,3072]
    const float* b_qkv  = (const float*)d_in[3];   // [3072]
    float* out = (float*)d_out;

    (void)in_sizes; (void)n_in; (void)out_size;

    compact_kernel<<<8, 256>>>(mask);

    int n4 = NX4 + NW4;
    preconv_kernel<<<(n4 + 255) / 256, 256>>>(hidden, w_qkv);

    size_t smem1 = 512 + 2 * (size_t)BUF2;         // 59904
    cudaFuncSetAttribute(qkv_gemm_kernel,
                         cudaFuncAttributeMaxDynamicSharedMemorySize, (int)smem1);
    dim3 g1(48, 64);
    qkv_gemm_kernel<<<g1, 256, smem1>>>(b_qkv);

    // smem: Qh+Ql (2*128*72) + Kh+Kl (2*64*72) + Vh (64*72) halfs = 64512 B
    size_t smem2 = (size_t)(128 * QSH * 2 + 64 * QSH * 3) * sizeof(__half);
    cudaFuncSetAttribute(attn_kernel,
                         cudaFuncAttributeMaxDynamicSharedMemorySize, (int)smem2);
    dim3 g2(S_ / 128, BH_);                         // 8 x 128
    attn_kernel<<<g2, 256, smem2>>>(out);
}